// round 2
// baseline (speedup 1.0000x reference)
#include <cuda_runtime.h>
#include <cstdint>

#define T_SEQ 2048
#define NB    64
#define DIN   256
#define NH    256

// scratch: precomputed input projection xw[t][b][h]  (128 MB, static — no allocs)
__device__ float g_xw[(size_t)T_SEQ * NB * NH];

// ---------------- packed fp32x2 helpers (sm_100+) ----------------
__device__ __forceinline__ unsigned long long fma2(unsigned long long a,
                                                   unsigned long long b,
                                                   unsigned long long c) {
    unsigned long long d;
    asm("fma.rn.f32x2 %0, %1, %2, %3;" : "=l"(d) : "l"(a), "l"(b), "l"(c));
    return d;
}
__device__ __forceinline__ float f2sum(unsigned long long v) {
    float lo, hi;
    asm("mov.b64 {%0, %1}, %2;" : "=f"(lo), "=f"(hi) : "l"(v));
    return lo + hi;
}
__device__ __forceinline__ uint32_t smem_u32(const void* p) {
    uint32_t a;
    asm("{.reg .u64 t; cvta.to.shared.u64 t, %1; cvt.u32.u64 %0, t;}"
        : "=r"(a) : "l"(p));
    return a;
}
__device__ __forceinline__ uint32_t mapa_(uint32_t addr, int rank) {
    uint32_t r;
    asm("mapa.shared::cluster.u32 %0, %1, %2;" : "=r"(r) : "r"(addr), "r"(rank));
    return r;
}
__device__ __forceinline__ void cluster_sync_() {
    asm volatile("barrier.cluster.arrive.aligned;\n\t"
                 "barrier.cluster.wait.aligned;" ::: "memory");
}
// acquire(cluster)-wait on local mbarrier for given phase parity
__device__ __forceinline__ void mbar_wait(uint32_t addr, int parity) {
    asm volatile(
        "{\n\t.reg .pred P;\n\t"
        "WLOOP%=:\n\t"
        "mbarrier.try_wait.parity.acquire.cluster.shared::cta.b64 P, [%0], %1, 0x989680;\n\t"
        "@P bra WDONE%=;\n\t"
        "bra WLOOP%=;\n\t"
        "WDONE%=:\n\t}"
        :: "r"(addr), "r"(parity) : "memory");
}

// =================================================================
// Kernel 1: input projection  g_xw[row][j] = x[row]·w_ih[j] + b_ih[j] + b_hh[j]
// (unchanged from R1 — issue-bound, ~300us)
// =================================================================
__global__ void __launch_bounds__(256, 1)
xw_kernel(const float* __restrict__ x,
          const float* __restrict__ w_ih,
          const float* __restrict__ b_ih,
          const float* __restrict__ b_hh) {
    __shared__ __align__(16) float xs[8][256];
    __shared__ float pbuf[8 * 512];

    const int tid  = threadIdx.x;
    const int w    = tid >> 5;
    const int lane = tid & 31;
    const int kg   = w >> 1;
    const int og   = ((w & 1) << 5) | lane;
    const int half = blockIdx.y;
    const int rowbase0 = blockIdx.x * 128;

    unsigned long long wa[32], wb[32];
    {
        const int j0 = half * 128 + og, j1 = j0 + 64;
        const unsigned long long* p0 =
            (const unsigned long long*)(w_ih + (size_t)j0 * DIN + kg * 64);
        const unsigned long long* p1 =
            (const unsigned long long*)(w_ih + (size_t)j1 * DIN + kg * 64);
#pragma unroll
        for (int i = 0; i < 32; i++) { wa[i] = p0[i]; wb[i] = p1[i]; }
    }
    float bias = 0.f;
    if (tid < 128) bias = b_ih[half * 128 + tid] + b_hh[half * 128 + tid];

    const float4* xg = (const float4*)x;
    {
        int q = tid, r = q >> 6, c4 = q & 63;
        ((float4*)xs)[q]       = xg[(size_t)(rowbase0 + r) * 64 + c4];
        ((float4*)xs)[q + 256] = xg[(size_t)(rowbase0 + 4 + r) * 64 + c4];
    }
    __syncthreads();

    for (int it = 0; it < 16; it++) {
        const int rowbase = rowbase0 + it * 8;
        float4 n0, n1;
        if (it < 15) {
            int q = tid, r = q >> 6, c4 = q & 63;
            int nrb = rowbase + 8;
            n0 = xg[(size_t)(nrb + r) * 64 + c4];
            n1 = xg[(size_t)(nrb + 4 + r) * 64 + c4];
        }
        unsigned long long acc[8][2];
#pragma unroll
        for (int r = 0; r < 8; r++) { acc[r][0] = 0ull; acc[r][1] = 0ull; }
#pragma unroll
        for (int r = 0; r < 8; r++) {
            const ulonglong2* xp = (const ulonglong2*)&xs[r][kg * 64];
#pragma unroll
            for (int i = 0; i < 16; i++) {
                ulonglong2 hv = xp[i];
                acc[r][0] = fma2(wa[2 * i],     hv.x, acc[r][0]);
                acc[r][0] = fma2(wa[2 * i + 1], hv.y, acc[r][0]);
                acc[r][1] = fma2(wb[2 * i],     hv.x, acc[r][1]);
                acc[r][1] = fma2(wb[2 * i + 1], hv.y, acc[r][1]);
            }
        }
#pragma unroll
        for (int r = 0; r < 8; r++) {
            pbuf[r * 512 + kg * 128 + og]      = f2sum(acc[r][0]);
            pbuf[r * 512 + kg * 128 + og + 64] = f2sum(acc[r][1]);
        }
        __syncthreads();
        if (it < 15) {
            int q = tid;
            ((float4*)xs)[q]       = n0;
            ((float4*)xs)[q + 256] = n1;
        }
        if (tid < 128) {
#pragma unroll
            for (int r = 0; r < 8; r++) {
                float s = pbuf[r * 512 + tid] + pbuf[r * 512 + 128 + tid] +
                          pbuf[r * 512 + 256 + tid] + pbuf[r * 512 + 384 + tid] + bias;
                g_xw[(size_t)(rowbase + r) * NH + half * 128 + tid] = s;
            }
        }
        __syncthreads();
    }
}

// =================================================================
// Kernel 2: persistent recurrence, v2.
//   64 clusters x 2 CTAs, 256 thr. CTA c owns outputs Jc=[c*128, c*128+128).
//   Warp w: 16 cols, lane pair (2q, 2q+1) k-splits each col (kh = lane&1).
//   Each thread: 64 local-k + 64 remote-k weights in regs (128 floats).
//   Per step: local-k FMA -> mbarrier wait (peer h pushes) -> remote-k FMA
//   -> shfl reduce -> tanh -> local store + DSMEM push + arrive(release).
// =================================================================
__global__ void __launch_bounds__(256, 1) __cluster_dims__(2, 1, 1)
rnn_kernel(const float* __restrict__ w_hh, float* __restrict__ out) {
    __shared__ __align__(16) float hbuf[2][256];
    __shared__ __align__(8) unsigned long long rbar;   // remote-ready mbarrier

    const int tid  = threadIdx.x;
    const int w    = tid >> 5;
    const int l    = tid & 31;
    const int kh   = l & 1;                    // k-half within the pair
    const int jl   = w * 16 + (l >> 1);        // local output col 0..127
    const int b    = blockIdx.x >> 1;          // batch row
    const int c    = blockIdx.x & 1;           // cluster rank
    const int peer = c ^ 1;
    const int j    = c * 128 + jl;             // global output col

    // register-resident weights for row j:
    //   wl: k in [c*128 + kh*64, +64)   (local h half)
    //   wr: k in [peer*128 + kh*64, +64) (remote h half)
    unsigned long long wl[32], wr[32];
    {
        const float* wrow = w_hh + (size_t)j * NH;
        const unsigned long long* pl =
            (const unsigned long long*)(wrow + c * 128 + kh * 64);
        const unsigned long long* pr =
            (const unsigned long long*)(wrow + peer * 128 + kh * 64);
#pragma unroll
        for (int i = 0; i < 32; i++) { wl[i] = pl[i]; wr[i] = pr[i]; }
    }

    hbuf[0][tid] = 0.f;                        // h0 = 0
    const uint32_t bar = smem_u32(&rbar);
    if (tid == 0) {
        asm volatile("mbarrier.init.shared.b64 [%0], 8;" :: "r"(bar) : "memory");
    }

    // precomputed peer addresses (mapa once)
    const uint32_t ph0 = mapa_(smem_u32(&hbuf[0][j]), peer);
    const uint32_t ph1 = mapa_(smem_u32(&hbuf[1][j]), peer);
    const uint32_t pbar = mapa_(bar, peer);

    cluster_sync_();   // mbarrier init + hbuf[0]=0 visible cluster-wide

    const bool writer = (kh == 0);
    float xw_cur = 0.f, xw_n1 = 0.f;
    if (writer) {
        xw_cur = __ldg(&g_xw[(size_t)b * NH + j]);
        xw_n1  = __ldg(&g_xw[((size_t)NB + b) * NH + j]);
    }

    int p = 0, phase = 0;
    for (int s = 0; s < T_SEQ; s++) {
        float xw_n2 = 0.f;
        if (writer && s + 2 < T_SEQ)
            xw_n2 = __ldg(&g_xw[((size_t)(s + 2) * NB + b) * NH + j]);

        // ---- local-k half: h produced by own CTA (ready after last bar) ----
        unsigned long long a0 = 0ull, a1 = 0ull;
        {
            const ulonglong2* hp =
                (const ulonglong2*)&hbuf[p][c * 128 + kh * 64];
#pragma unroll
            for (int i = 0; i < 16; i++) {
                ulonglong2 hv = hp[i];
                a0 = fma2(wl[2 * i],     hv.x, a0);
                a1 = fma2(wl[2 * i + 1], hv.y, a1);
            }
        }

        // ---- wait for peer's h pushes for this step ----
        if (s) { mbar_wait(bar, phase); phase ^= 1; }

        // ---- remote-k half ----
        {
            const ulonglong2* hp =
                (const ulonglong2*)&hbuf[p][peer * 128 + kh * 64];
#pragma unroll
            for (int i = 0; i < 16; i++) {
                ulonglong2 hv = hp[i];
                a0 = fma2(wr[2 * i],     hv.x, a0);
                a1 = fma2(wr[2 * i + 1], hv.y, a1);
            }
        }

        float v0 = f2sum(a0) + f2sum(a1);
        float sum = v0 + __shfl_xor_sync(0xffffffffu, v0, 1);

        if (writer) {
            float v = tanhf(sum + xw_cur);
            hbuf[p ^ 1][j] = v;                              // local copy
            uint32_t ra = p ? ph0 : ph1;                     // peer copy (push)
            asm volatile("st.shared::cluster.f32 [%0], %1;"
                         :: "r"(ra), "f"(v) : "memory");
            out[((size_t)s * NB + b) * NH + j] = v;
            xw_cur = xw_n1;
            xw_n1  = xw_n2;
        }
        if (s + 1 < T_SEQ) {
            __syncwarp();
            if (l == 0) {   // one release-arrive per warp on peer's barrier
                asm volatile(
                    "mbarrier.arrive.release.cluster.shared::cluster.b64 _, [%0];"
                    :: "r"(pbar) : "memory");
            }
        }
        __syncthreads();   // local h half visible CTA-wide; hbuf[p] reuse safe
        p ^= 1;
    }
    cluster_sync_();   // no CTA exits while peer ops may be in flight
}

// =================================================================
extern "C" void kernel_launch(void* const* d_in, const int* in_sizes, int n_in,
                              void* d_out, int out_size) {
    const float* x    = (const float*)d_in[0];
    const float* w_ih = (const float*)d_in[1];
    const float* w_hh = (const float*)d_in[2];
    const float* b_ih = (const float*)d_in[3];
    const float* b_hh = (const float*)d_in[4];
    float* out = (float*)d_out;

    dim3 g1(1024, 2);
    xw_kernel<<<g1, 256>>>(x, w_ih, b_ih, b_hh);
    rnn_kernel<<<128, 256>>>(w_hh, out);
}